// round 15
// baseline (speedup 1.0000x reference)
#include <cuda_runtime.h>

#define D_TOT 65536
#define S_TOT 1024
#define TSZ   32
#define NT    (S_TOT / TSZ)   // 32 tiles
#define DW    64              // d-columns per block
#define PAD   68              // tile row stride (floats); 16B-aligned rows
#define NBLK  1025            // d in [64b-1, 64b+62] -> float4 hvs stores aligned
#define EPS   0.02f           // |bundled| below this -> precise-trig recompute

__device__ float        g_part[NBLK];
__device__ unsigned int g_ctr;   // zero at load; reset by the reducing block each call

// R9 pipeline scaled to 64-wide d: enc tile held [s][d] so the store phase
// reads smem rows contiguously and writes hvs as ALIGNED float4 -> 256B
// warp-store spans (2x DRAM page locality, half the store instructions).
// TS=32 ping-pong keeps smem at 26.9KB (occ 6) with one barrier per tile.
// d-tiling shifted by -1 (hvs data starts at element 65537) so stores are
// 16B-aligned; blocks 0 and 1024 take a guarded scalar edge path.
__global__ __launch_bounds__(256, 6) void reghd_main(
    const float* __restrict__ x,
    const float* __restrict__ weight,
    const float* __restrict__ bias,
    const float* __restrict__ alpha,
    const float* __restrict__ M,
    float* __restrict__ out)   // [0]=model_result, [1..D]=q, [1+D ...]=hvs (SIZE,D)
{
    __shared__ float4 sx4[S_TOT / 4];
    __shared__ float4 sa4[S_TOT / 4];
    __shared__ float  tile[2][TSZ][PAD];   // [s][d], 17.4KB total
    __shared__ float  bpart[DW];
    __shared__ float  qsum[2];
    __shared__ float  red[256];
    __shared__ bool   is_last;

    const int tid = threadIdx.x;            // 0..255
    const int tx  = tid & 31;
    const int ty  = tid >> 5;                // warp id 0..7
    const int db  = (int)blockIdx.x * DW - 1;
    const bool edge = (blockIdx.x == 0) || (blockIdx.x == NBLK - 1);

    // compute-phase mapping: 4 threads per d-row
    const int dl = tid >> 2;                 // d-row 0..63
    const int c  = tid & 3;                  // s-segment 0..3
    const int d  = db + dl;
    const bool drow_ok = (unsigned)d < (unsigned)D_TOT;

    // store-phase mapping
    const int m = tx & 15;                   // float4 column 0..15
    const int h = tx >> 4;                   // row-half 0..1

    sx4[tid] = ((const float4*)x)[tid];
    sa4[tid] = ((const float4*)alpha)[tid];
    __syncthreads();

    float acc = 0.f;                          // bundled partial for row dl
    float* __restrict__ hvs = out + 1 + D_TOT;

    int p = 0;
    for (int t = 0; t < NT; t++) {
        const int s0 = t * TSZ;

        #pragma unroll
        for (int j = 0; j < 2; j++) {
            const int sl4 = 4 * (c + 4 * j);            // 0..28
            if (drow_ok) {
                const size_t base = (size_t)d * S_TOT + (size_t)(s0 + sl4);
                const float4 w  = __ldcs((const float4*)(weight + base));
                const float4 b  = __ldcs((const float4*)(bias   + base));
                const float4 xv = sx4[(s0 + sl4) >> 2];
                const float4 av = sa4[(s0 + sl4) >> 2];

                const float p0 = xv.x * w.x, p1 = xv.y * w.y;
                const float p2 = xv.z * w.z, p3 = xv.w * w.w;
                const float e0 = __cosf(p0 + b.x) * __sinf(p0);
                const float e1 = __cosf(p1 + b.y) * __sinf(p1);
                const float e2 = __cosf(p2 + b.z) * __sinf(p2);
                const float e3 = __cosf(p3 + b.w) * __sinf(p3);

                tile[p][sl4 + 0][dl] = e0;   // [s][d] layout: transposed STS
                tile[p][sl4 + 1][dl] = e1;
                tile[p][sl4 + 2][dl] = e2;
                tile[p][sl4 + 3][dl] = e3;

                acc += fmaf(e0, av.x, fmaf(e1, av.y, fmaf(e2, av.z, e3 * av.w)));
            }
        }

        __syncthreads();   // tile[p] complete; also fences buf[p^1] reuse

        #pragma unroll
        for (int k = 0; k < 2; k++) {
            const int   row = 16 * k + 2 * ty + h;       // s-row 0..31, disjoint cover
            const float4 v  = *(const float4*)&tile[p][row][4 * m];
            const size_t o  = (size_t)(s0 + row) * D_TOT + (size_t)(db + 4 * m);
            if (!edge) {
                __stcs((float4*)&hvs[o], v);             // aligned 16B store
            } else {
                const float ve[4] = {v.x, v.y, v.z, v.w};
                #pragma unroll
                for (int i = 0; i < 4; i++) {
                    const int dd = db + 4 * m + i;
                    if ((unsigned)dd < (unsigned)D_TOT)
                        __stcs(&hvs[(size_t)(s0 + row) * D_TOT + dd], ve[i]);
                }
            }
        }
        p ^= 1;            // no barrier: next compute targets the other buffer
    }

    // Combine the 4 per-row threads (lanes 4r..4r+3): xor 1,2 keep groups separate.
    float v = acc;
    v += __shfl_xor_sync(0xFFFFFFFFu, v, 1);
    v += __shfl_xor_sync(0xFFFFFFFFu, v, 2);
    if (c == 0) bpart[dl] = v;                // full row total
    __syncthreads();

    // Warps 0-1: guarded sign, q, dot(q,M) partial (32 rows each).
    if (ty < 2) {
        const int  row    = 32 * ty + tx;
        const int  dq     = db + row;
        const bool dvalid = (unsigned)dq < (unsigned)D_TOT;
        float vv = bpart[row];

        // Ballot-driven precise fallback: per-warp loop, full-mask legal.
        unsigned flag = __ballot_sync(0xFFFFFFFFu, dvalid && fabsf(vv) < EPS);
        const float* xs = (const float*)sx4;
        const float* as = (const float*)sa4;
        while (flag) {
            const int r = __ffs(flag) - 1;
            flag &= flag - 1;
            const int dr = db + 32 * ty + r;
            float s2 = 0.f;
            for (int s = tx; s < S_TOT; s += 32) {
                const float wv = weight[(size_t)dr * S_TOT + s];
                const float bv = bias[(size_t)dr * S_TOT + s];
                const float pp = xs[s] * wv;
                s2 += cosf(pp + bv) * sinf(pp) * as[s];
            }
            #pragma unroll
            for (int off = 16; off > 0; off >>= 1)
                s2 += __shfl_xor_sync(0xFFFFFFFFu, s2, off);
            if (tx == r) vv = s2;
        }

        float qm = 0.f;
        if (dvalid) {
            const float q = (vv > 0.f) ? 1.f : -1.f;
            out[1 + dq] = q;
            qm = q * M[dq];
        }
        #pragma unroll
        for (int off = 16; off > 0; off >>= 1)
            qm += __shfl_xor_sync(0xFFFFFFFFu, qm, off);
        if (tx == 0) qsum[ty] = qm;
    }
    __syncthreads();
    if (tid == 0) {
        g_part[blockIdx.x] = qsum[0] + qsum[1];
        __threadfence();
        const unsigned int prev = atomicAdd(&g_ctr, 1u);
        is_last = (prev == NBLK - 1);
    }
    __syncthreads();

    // Last-arriving block reduces all partials (fixed order -> deterministic).
    if (is_last) {
        float s = 0.f;
        for (int i = tid; i < NBLK; i += 256)
            s += g_part[i];
        red[tid] = s;
        __syncthreads();
        #pragma unroll
        for (int k = 128; k > 0; k >>= 1) {
            if (tid < k) red[tid] += red[tid + k];
            __syncthreads();
        }
        if (tid == 0) {
            out[0] = red[0];
            g_ctr  = 0;          // reset for next graph replay
        }
    }
}

extern "C" void kernel_launch(void* const* d_in, const int* in_sizes, int n_in,
                              void* d_out, int out_size) {
    const float* x      = (const float*)d_in[0];
    const float* weight = (const float*)d_in[1];
    const float* bias   = (const float*)d_in[2];
    const float* alpha  = (const float*)d_in[3];
    const float* M      = (const float*)d_in[4];
    float* out = (float*)d_out;

    reghd_main<<<NBLK, 256>>>(x, weight, bias, alpha, M, out);
}

// round 16
// speedup vs baseline: 1.2275x; 1.2275x over previous
#include <cuda_runtime.h>

#define D_TOT 65536
#define S_TOT 1024
#define NT    16             // 16 iterations x 64 s (32 per group)
#define NBLK  (D_TOT / 32)   // 2048 blocks
#define EPS   0.02f          // |bundled| below this -> precise-trig recompute

__device__ float        g_part[NBLK];
__device__ unsigned int g_ctr;   // zero at load; reset by the reducing block each call

#define BAR_GRP(id) asm volatile("bar.sync %0, 128;" :: "r"(id) : "memory")

// R9 (26KB smem, occ 6, ping-pong transpose, one barrier/tile) with the
// barrier scope halved: warps 0-3 and 4-7 form independent groups, each
// owning one 32-s half of every tile with a private ping-pong buffer and a
// private named barrier (bar.sync 1/2, 128 threads). The halves drift
// freely through the whole mainloop -> half the lockstep degree at
// identical footprint, store width, and traffic.
__global__ __launch_bounds__(256, 6) void reghd_main(
    const float* __restrict__ x,
    const float* __restrict__ weight,
    const float* __restrict__ bias,
    const float* __restrict__ alpha,
    const float* __restrict__ M,
    float* __restrict__ out)   // [0]=model_result, [1..D]=q, [1+D ...]=hvs (SIZE,D)
{
    __shared__ float sx[S_TOT];
    __shared__ float sa[S_TOT];
    __shared__ float tile[2][2][32][33];  // [group][buf][d][s half], 16.9KB
    __shared__ float bpart[2][32];        // per-group bundled partials
    __shared__ float red[256];
    __shared__ bool  is_last;

    const int tx  = threadIdx.x;          // 0..31
    const int ty  = threadIdx.y;          // 0..7
    const int tid = ty * 32 + tx;
    const int d0  = blockIdx.x * 32;
    const int g   = ty >> 2;              // group 0/1
    const int w   = ty & 3;               // warp within group
    const int j   = tx >> 3;              // 0..3
    const int m   = tx & 7;               // 0..7
    const int sc  = 4 * m;                // s within 32-s half (0..28)

    ((float4*)sx)[tid] = ((const float4*)x)[tid];
    ((float4*)sa)[tid] = ((const float4*)alpha)[tid];
    __syncthreads();

    // Thread's two d-rows: dl = w + 4j + 16r (r=0,1); covers 0..31 per group.
    float acc[2] = {0.f, 0.f};
    float* __restrict__ hvs = out + 1 + D_TOT;

    int p = 0;
    for (int t = 0; t < NT; t++) {
        const int s0 = t * 64 + 32 * g;   // this group's s-half base

        #pragma unroll
        for (int r = 0; r < 2; r++) {
            const int    dl   = w + 4 * j + 16 * r;
            const size_t base = (size_t)(d0 + dl) * S_TOT + (size_t)(s0 + sc);
            const float4 w4 = __ldcs((const float4*)(weight + base));
            const float4 b4 = __ldcs((const float4*)(bias   + base));
            const float  x0 = sx[s0 + sc], x1 = sx[s0 + sc + 1];
            const float  x2 = sx[s0 + sc + 2], x3 = sx[s0 + sc + 3];

            const float p0 = x0 * w4.x, p1 = x1 * w4.y;
            const float p2 = x2 * w4.z, p3 = x3 * w4.w;
            const float e0 = __cosf(p0 + b4.x) * __sinf(p0);
            const float e1 = __cosf(p1 + b4.y) * __sinf(p1);
            const float e2 = __cosf(p2 + b4.z) * __sinf(p2);
            const float e3 = __cosf(p3 + b4.w) * __sinf(p3);

            tile[g][p][dl][sc + 0] = e0;
            tile[g][p][dl][sc + 1] = e1;
            tile[g][p][dl][sc + 2] = e2;
            tile[g][p][dl][sc + 3] = e3;

            acc[r] += fmaf(e0, sa[s0 + sc],     fmaf(e1, sa[s0 + sc + 1],
                      fmaf(e2, sa[s0 + sc + 2],      e3 * sa[s0 + sc + 3])));
        }

        BAR_GRP(g + 1);   // group-local: publish tile[g][p]; fence buf reuse

        #pragma unroll
        for (int k = 0; k < 8; k++) {
            const int sl = w + 4 * k;     // 4 warps x 8 -> 32 s-rows of the half
            __stcs(&hvs[(size_t)(s0 + sl) * D_TOT + (size_t)(d0 + tx)],
                   tile[g][p][tx][sl]);   // (tx+sl) banks: conflict-free
        }
        p ^= 1;           // next compute targets the other buffer — no barrier
    }

    // Reduce acc over the 8 lanes sharing a row (xor on low 3 bits).
    #pragma unroll
    for (int r = 0; r < 2; r++) {
        float v = acc[r];
        v += __shfl_xor_sync(0xFFFFFFFFu, v, 1);
        v += __shfl_xor_sync(0xFFFFFFFFu, v, 2);
        v += __shfl_xor_sync(0xFFFFFFFFu, v, 4);
        if (m == 0) bpart[g][w + 4 * j + 16 * r] = v;
    }
    __syncthreads();

    // Warp 0: combine group halves, guarded sign, q, dot(q,M) partial.
    if (ty == 0) {
        float v = bpart[0][tx] + bpart[1][tx];

        // Ballot-driven precise fallback: warp-uniform loop, full-mask legal.
        unsigned flag = __ballot_sync(0xFFFFFFFFu, fabsf(v) < EPS);
        while (flag) {
            const int r = __ffs(flag) - 1;
            flag &= flag - 1;
            const int d = d0 + r;
            float s2 = 0.f;
            for (int s = tx; s < S_TOT; s += 32) {
                const float wv = weight[(size_t)d * S_TOT + s];
                const float bv = bias[(size_t)d * S_TOT + s];
                const float pp = sx[s] * wv;
                s2 += cosf(pp + bv) * sinf(pp) * sa[s];
            }
            #pragma unroll
            for (int off = 16; off > 0; off >>= 1)
                s2 += __shfl_xor_sync(0xFFFFFFFFu, s2, off);
            if (tx == r) v = s2;
        }

        const float q = (v > 0.f) ? 1.f : -1.f;
        out[1 + d0 + tx] = q;
        float qm = q * M[d0 + tx];
        #pragma unroll
        for (int off = 16; off > 0; off >>= 1)
            qm += __shfl_xor_sync(0xFFFFFFFFu, qm, off);
        if (tx == 0) {
            g_part[blockIdx.x] = qm;
            __threadfence();
            const unsigned int prev = atomicAdd(&g_ctr, 1u);
            is_last = (prev == NBLK - 1);
        }
    }
    __syncthreads();

    // Last-arriving block reduces all partials (fixed order -> deterministic).
    if (is_last) {
        float s = 0.f;
        for (int i = tid; i < NBLK; i += 256)
            s += g_part[i];
        red[tid] = s;
        __syncthreads();
        #pragma unroll
        for (int k = 128; k > 0; k >>= 1) {
            if (tid < k) red[tid] += red[tid + k];
            __syncthreads();
        }
        if (tid == 0) {
            out[0] = red[0];
            g_ctr  = 0;          // reset for next graph replay
        }
    }
}

extern "C" void kernel_launch(void* const* d_in, const int* in_sizes, int n_in,
                              void* d_out, int out_size) {
    const float* x      = (const float*)d_in[0];
    const float* weight = (const float*)d_in[1];
    const float* bias   = (const float*)d_in[2];
    const float* alpha  = (const float*)d_in[3];
    const float* M      = (const float*)d_in[4];
    float* out = (float*)d_out;

    dim3 blk(32, 8);
    reghd_main<<<NBLK, blk>>>(x, weight, bias, alpha, M, out);
}